// round 15
// baseline (speedup 1.0000x reference)
#include <cuda_runtime.h>
#include <cuda_fp16.h>
#include <math.h>

#define Lc   256
#define Bc   128
#define Dc   512
#define Hc   512
#define G3c  1536      // 3*H
#define OUT2H 1024     // 2*H
#define MAXL 256
#define NROWS (Lc*Bc)  // 32768

// ------------------------- static device scratch ---------------------------
__device__ float g_xg[(size_t)2 * Lc * Bc * G3c];          // ~403 MB
__device__ float g_aprev[(size_t)NROWS * Hc];              // DT child sums (fp32)
__device__ __align__(16) __half g_emb16[(size_t)NROWS * Dc];      // fp16 emb [row][k]
__device__ __align__(16) __half g_U16[2][(size_t)G3c * Hc];       // fp16 Uh^T [n][k]
__device__ __align__(16) __half g_W16[2][(size_t)G3c * Hc];       // fp16 Wx^T [n][k]
__device__ int   g_lvl[2][Bc][Lc];
__device__ int   g_cnt[2][MAXL][Bc];
__device__ int   g_off[2][MAXL * Bc];
__device__ int   g_lvloff[2][MAXL + 1];
__device__ int   g_rows[2][NROWS];                         // (b<<16)|node
__device__ int   g_pos0[Bc][Lc];                           // DT node -> level pos
__device__ int   g_nlvl[2];
__device__ int   g_nsteps;
__device__ int   g_choff[Bc][Lc + 1];
__device__ int   g_chlist[Bc][Lc];

__device__ volatile unsigned g_gen;
__device__ unsigned g_barcnt;

__device__ __forceinline__ void gridbar() {
    __syncthreads();
    if (threadIdx.x == 0) {
        unsigned gen = g_gen;
        __threadfence();
        unsigned old = atomicInc(&g_barcnt, gridDim.x - 1);
        if (old == gridDim.x - 1) {
            __threadfence();
            g_gen = gen + 1;
        } else {
            while (g_gen == gen) { __nanosleep(32); }
            __threadfence();
        }
    }
    __syncthreads();
}

// ------------------------- helpers -----------------------------------------
__device__ __forceinline__ unsigned pack_h2(float a, float b) {
    __half2 h = __floats2half2_rn(a, b);
    return *(unsigned*)&h;
}
__device__ __forceinline__ void mma16(float* c, const unsigned* a, const unsigned* b) {
    asm volatile(
        "mma.sync.aligned.m16n8k16.row.col.f32.f16.f16.f32 "
        "{%0,%1,%2,%3},{%4,%5,%6,%7},{%8,%9},{%0,%1,%2,%3};\n"
        : "+f"(c[0]), "+f"(c[1]), "+f"(c[2]), "+f"(c[3])
        : "r"(a[0]), "r"(a[1]), "r"(a[2]), "r"(a[3]), "r"(b[0]), "r"(b[1]));
}
__device__ __forceinline__ void cpa16(void* smem, const void* g) {
    unsigned s = (unsigned)__cvta_generic_to_shared(smem);
    asm volatile("cp.async.cg.shared.global [%0], [%1], 16;\n" :: "r"(s), "l"(g));
}
__device__ __forceinline__ void cpa_commit() {
    asm volatile("cp.async.commit_group;\n");
}
template <int N> __device__ __forceinline__ void cpa_wait() {
    asm volatile("cp.async.wait_group %0;\n" :: "n"(N));
}
__device__ __forceinline__ float sigf(float x) { return 1.f / (1.f + __expf(-x)); }
__device__ __forceinline__ float tanhfast(float x) { return 2.f * sigf(2.f * x) - 1.f; }

// ---------------- merged pre-pass: zero + emb cvt + weight transposes -------
// blocks [0,8192): emb fp16 cvt | [8192,11264): 4 transposes (768 tiles each)
// | [11264,19456): zero g_aprev.
__global__ __launch_bounds__(256) void PcvtAll(
    const float* __restrict__ emb,
    const float* __restrict__ U0, const float* __restrict__ U1,
    const float* __restrict__ W0, const float* __restrict__ W1)
{
    const int bx = blockIdx.x;
    if (bx < 8192) {
        size_t i = ((size_t)bx * 256 + threadIdx.x) * 8;
        float4 v0 = *(const float4*)&emb[i];
        float4 v1 = *(const float4*)&emb[i + 4];
        uint4 u;
        u.x = pack_h2(v0.x, v0.y); u.y = pack_h2(v0.z, v0.w);
        u.z = pack_h2(v1.x, v1.y); u.w = pack_h2(v1.z, v1.w);
        *(uint4*)&g_emb16[i] = u;
    } else if (bx < 11264) {
        __shared__ float sm[32][33];
        const int r = bx - 8192;
        const int w = r / 768;
        const int rr = r - w * 768;
        const float* src = (w == 0) ? U0 : (w == 1) ? U1 : (w == 2) ? W0 : W1;
        __half* dst = (w == 0) ? g_U16[0] : (w == 1) ? g_U16[1]
                    : (w == 2) ? g_W16[0] : g_W16[1];
        const int n0 = (rr % 48) * 32, k0 = (rr / 48) * 32;
        const int tx = threadIdx.x & 31, ty = threadIdx.x >> 5;
#pragma unroll
        for (int i = 0; i < 4; i++)
            sm[ty + 8 * i][tx] = src[(size_t)(k0 + ty + 8 * i) * G3c + n0 + tx];
        __syncthreads();
#pragma unroll
        for (int i = 0; i < 4; i++)
            dst[(size_t)(n0 + ty + 8 * i) * Hc + k0 + tx] =
                __float2half_rn(sm[tx][ty + 8 * i]);
    } else {
        size_t i = ((size_t)(bx - 11264) * 256 + threadIdx.x) * 8;
        float4 z = make_float4(0.f, 0.f, 0.f, 0.f);
        *(float4*)&g_aprev[i] = z;
        *(float4*)&g_aprev[i + 4] = z;
    }
}

// --------------------------- preprocessing ---------------------------------
__global__ __launch_bounds__(256) void Pprep(const int* __restrict__ pidx) {
    __shared__ int par[256], anc[256], dst[256], hgt[256];
    __shared__ int c0[256], c1[256], tmpc[256], cur[256], loff[257];
    __shared__ int mxd;
    const int b = blockIdx.x, i = threadIdx.x;
    par[i] = (i == 0) ? 0 : pidx[i * Bc + b];
    c0[i] = 0; c1[i] = 0; tmpc[i] = 0; hgt[i] = 0;
    if (i == 0) mxd = 0;
    __syncthreads();
    anc[i] = par[i];
    dst[i] = (i == 0) ? 0 : 1;
    __syncthreads();
#pragma unroll
    for (int r = 0; r < 8; ++r) {
        int a = anc[i];
        int nd = dst[i] + dst[a];
        int na = anc[a];
        __syncthreads();
        dst[i] = nd; anc[i] = na;
        __syncthreads();
    }
    const int depth = dst[i];
    atomicMax(&mxd, depth);
    if (i == 0) {
        for (int j = 255; j >= 1; --j) {
            int p = par[j], v = hgt[j] + 1;
            if (v > hgt[p]) hgt[p] = v;
        }
    }
    __syncthreads();
    const int h = hgt[i];
    atomicAdd(&c0[h], 1);
    atomicAdd(&c1[depth], 1);
    g_lvl[0][b][i] = h;
    g_lvl[1][b][i] = depth;
    if (i > 0) atomicAdd(&tmpc[par[i]], 1);
    __syncthreads();
    g_cnt[0][i][b] = c0[i];
    g_cnt[1][i][b] = c1[i];
    if (i == 0) {
        atomicMax(&g_nlvl[0], hgt[0] + 1);
        atomicMax(&g_nlvl[1], mxd + 1);
        int run = 0;
        loff[0] = 0;
        for (int p2 = 0; p2 < Lc; ++p2) {
            run += tmpc[p2]; loff[p2 + 1] = run; cur[p2] = 0;
        }
        for (int j = 1; j < Lc; ++j) {
            int p2 = par[j];
            g_chlist[b][loff[p2] + cur[p2]++] = j;
        }
    }
    __syncthreads();
    g_choff[b][i] = loff[i];
    if (i == 0) g_choff[b][Lc] = loff[Lc];
}

// exclusive scan; one block per pass, counts cached in registers (int4 loads)
__global__ __launch_bounds__(1024) void Pscan3() {
    __shared__ int wsum[32];
    const int p = blockIdx.x;
    const int tid = threadIdx.x;
    const int lane = tid & 31, wid = tid >> 5;
    const int* cnt = &g_cnt[p][0][0];
    int* off = &g_off[p][0];
    const int base = tid * 32;
    int vals[32];
#pragma unroll
    for (int k = 0; k < 8; ++k) {
        int4 v = *(const int4*)&cnt[base + k * 4];
        vals[k * 4 + 0] = v.x; vals[k * 4 + 1] = v.y;
        vals[k * 4 + 2] = v.z; vals[k * 4 + 3] = v.w;
    }
    int s = 0;
#pragma unroll
    for (int k = 0; k < 32; ++k) s += vals[k];
    int v = s;
#pragma unroll
    for (int d = 1; d < 32; d <<= 1) {
        int t2 = __shfl_up_sync(0xffffffffu, v, d);
        if (lane >= d) v += t2;
    }
    if (lane == 31) wsum[wid] = v;
    __syncthreads();
    if (wid == 0) {
        int w = wsum[lane];
#pragma unroll
        for (int d = 1; d < 32; d <<= 1) {
            int t2 = __shfl_up_sync(0xffffffffu, w, d);
            if (lane >= d) w += t2;
        }
        wsum[lane] = w;
    }
    __syncthreads();
    int run = v - s + (wid ? wsum[wid - 1] : 0);
    if ((tid & 3) == 0) g_lvloff[p][tid >> 2] = run;
#pragma unroll
    for (int k = 0; k < 32; ++k) { off[base + k] = run; run += vals[k]; }
    if (tid == 0) {
        g_lvloff[p][MAXL] = NROWS;
        if (p == 0) {
            int a = g_nlvl[0], c = g_nlvl[1];
            g_nsteps = a > c ? a : c;
        }
    }
}

// ---------------------------------------------------------------------------
// mega: [scatter preamble (blocks 0..255)] -> phase X (xg GEMM, grid-stride)
// -> full grid barrier -> unified wavefront with level-0 shortcut + scatter-
// add child sums (R14-proven). fp16 mma m16n8k16 throughout.
//
// shared carve (42240 B):
//   scatter:  lv @0 (1024) | lo @1024 (1024) | cur @2048 (1024)
//   phase X:  XA @0 (20480) | XB @20480 (20480)
//   levels:   A2s @0 (10240) | B2s/Cst @10240 (30720) | tables @40960 (1280)
// ---------------------------------------------------------------------------
__global__ __launch_bounds__(256, 2) void mega(
    const int* __restrict__ pidx, const float* __restrict__ pvalid,
    const float* __restrict__ bias0, const float* __restrict__ bias1,
    float* __restrict__ out)
{
    __shared__ __align__(16) char smraw[42240];
    unsigned* XA = (unsigned*)smraw;                     // [2][128*20]
    unsigned* XB = (unsigned*)(smraw + 20480);           // [2][128*20]
    unsigned* A2s = (unsigned*)smraw;                    // [2][64*20]
    unsigned* B2s = (unsigned*)(smraw + 10240);          // [2][192*20]
    float*    Cst = (float*)(smraw + 10240);             // [32*196] union B2s
    const float** rptr = (const float**)(smraw + 40960); // [64]
    float* rsc = (float*)(smraw + 41472);                // [64]
    int*   rpk = (int*)(smraw + 41728);                  // [64]
    int*   rpar = (int*)(smraw + 41984);                 // [64]

    const int tid = threadIdx.x;
    const int lane = tid & 31, wid = tid >> 5;
    const int g = lane >> 2, tg = lane & 3;
    const int wm = wid >> 2, wn = wid & 3;      // 2 x 4 warps

    // =================== scatter preamble (blocks 0..255) ===================
    if (blockIdx.x < 256) {
        int* slv = (int*)smraw;
        int* slo = (int*)(smraw + 1024);
        int* scur = (int*)(smraw + 2048);
        const int p = blockIdx.x >> 7, b = blockIdx.x & 127;
        slv[tid] = g_lvl[p][b][tid];
        slo[tid] = g_off[p][tid * Bc + b];
        scur[tid] = 0;
        __syncthreads();
        if (tid == 0) {
            for (int j = 0; j < Lc; ++j) {
                int l = slv[j];
                int pos = slo[l] + scur[l]++;
                g_rows[p][pos] = (b << 16) | j;
                if (p == 0) g_pos0[b][j] = pos;
            }
        }
        __syncthreads();
    }

    // =================== phase X: xg = emb @ Wx + b ===================
    for (int tt = blockIdx.x; tt < 6144; tt += gridDim.x) {
        const int pass = (tt >= 3072) ? 1 : 0;
        const int rem = tt - pass * 3072;
        const int ntile = rem % 12;
        const int mtile = rem / 12;
        const __half* __restrict__ W = g_W16[pass];
        const float* __restrict__ bias = pass ? bias1 : bias0;
        float* C = g_xg + (size_t)pass * Lc * Bc * G3c;
        const int m0 = mtile * 128, n0b = ntile * 128;

        float acc[4][4][4];
#pragma unroll
        for (int mi = 0; mi < 4; mi++)
#pragma unroll
            for (int ni = 0; ni < 4; ni++)
#pragma unroll
                for (int q = 0; q < 4; q++) acc[mi][ni][q] = 0.f;

        auto issue = [&](int c, int st) {
            const int kc = c << 5;
#pragma unroll
            for (int l2 = 0; l2 < 2; ++l2) {
                int slot = tid + (l2 << 8);
                int row = slot >> 2, q = slot & 3;
                cpa16(&XA[st * 2560 + row * 20 + q * 4],
                      g_emb16 + (size_t)(m0 + row) * Dc + kc + q * 8);
            }
#pragma unroll
            for (int l2 = 0; l2 < 2; ++l2) {
                int slot = tid + (l2 << 8);
                int row = slot >> 2, q = slot & 3;
                cpa16(&XB[st * 2560 + row * 20 + q * 4],
                      W + (size_t)(n0b + row) * Hc + kc + q * 8);
            }
            cpa_commit();
        };

        issue(0, 0);
        for (int c = 0; c < 16; ++c) {
            const int st = c & 1;
            if (c < 15) issue(c + 1, st ^ 1);
            if (c < 15) cpa_wait<1>(); else cpa_wait<0>();
            __syncthreads();
#pragma unroll
            for (int ss = 0; ss < 2; ++ss) {
                const int kpb = ss << 3;
                unsigned af[4][4], bf[4][2];
#pragma unroll
                for (int mi = 0; mi < 4; ++mi) {
                    int m = wm * 64 + mi * 16;
                    af[mi][0] = XA[st * 2560 + (m + g) * 20 + kpb + tg];
                    af[mi][1] = XA[st * 2560 + (m + g + 8) * 20 + kpb + tg];
                    af[mi][2] = XA[st * 2560 + (m + g) * 20 + kpb + tg + 4];
                    af[mi][3] = XA[st * 2560 + (m + g + 8) * 20 + kpb + tg + 4];
                }
#pragma unroll
                for (int ni = 0; ni < 4; ++ni) {
                    int nn = wn * 32 + ni * 8 + g;
                    bf[ni][0] = XB[st * 2560 + nn * 20 + kpb + tg];
                    bf[ni][1] = XB[st * 2560 + nn * 20 + kpb + tg + 4];
                }
#pragma unroll
                for (int mi = 0; mi < 4; ++mi)
#pragma unroll
                    for (int ni = 0; ni < 4; ++ni)
                        mma16(acc[mi][ni], af[mi], bf[ni]);
            }
            __syncthreads();
        }

#pragma unroll
        for (int mi = 0; mi < 4; ++mi)
#pragma unroll
            for (int ni = 0; ni < 4; ++ni) {
                int row = m0 + wm * 64 + mi * 16 + g;
                int col = n0b + wn * 32 + ni * 8 + 2 * tg;
                float b0v = bias[col], b1v = bias[col + 1];
                C[(size_t)row * G3c + col]           = acc[mi][ni][0] + b0v;
                C[(size_t)row * G3c + col + 1]       = acc[mi][ni][1] + b1v;
                C[(size_t)(row + 8) * G3c + col]     = acc[mi][ni][2] + b0v;
                C[(size_t)(row + 8) * G3c + col + 1] = acc[mi][ni][3] + b1v;
            }
        __syncthreads();
    }
    gridbar();   // xg + scatter results visible

    // =================== unified wavefront ===================
    const int nsteps = g_nsteps;

    for (int l = 0; l < nsteps; ++l) {
        const int s0 = g_lvloff[0][l], e0 = g_lvloff[0][l + 1];
        const int s1 = g_lvloff[1][l], e1 = g_lvloff[1][l + 1];
        const int n0 = e0 - s0, n1 = e1 - s1;

        if (l == 0) {
            // ---- level-0 shortcut + scatter-add to parents (DT) ----
            int total = (n0 + n1) << 7;   // 128 float4 per row
            for (int u = blockIdx.x * 256 + tid; u < total; u += gridDim.x * 256) {
                int rl = u >> 7, k4 = (u & 127) << 2;
                int p2, pos;
                if (rl < n0) { p2 = 0; pos = s0 + rl; }
                else         { p2 = 1; pos = s1 + (rl - n0); }
                int pk = g_rows[p2][pos];
                int b = pk >> 16, node = pk & 0xffff;
                const float* xrow = g_xg +
                    ((size_t)((p2 * Lc + node) * Bc + b)) * G3c;
                float4 xz = *(const float4*)&xrow[Hc + k4];
                float4 xn = *(const float4*)&xrow[2 * Hc + k4];
                float4 o;
                o.x = (1.f - sigf(xz.x)) * tanhfast(xn.x);
                o.y = (1.f - sigf(xz.y)) * tanhfast(xn.y);
                o.z = (1.f - sigf(xz.z)) * tanhfast(xn.z);
                o.w = (1.f - sigf(xz.w)) * tanhfast(xn.w);
                *(float4*)&out[((size_t)(b * Lc + node) << 10) + (p2 << 9) + k4] = o;
                if (p2 == 0) {
                    int par = pidx[node * Bc + b];
                    int ppos = g_pos0[b][par];
                    float* dst = g_aprev + ((size_t)ppos << 9) + k4;
                    atomicAdd(dst + 0, o.x);
                    atomicAdd(dst + 1, o.y);
                    atomicAdd(dst + 2, o.z);
                    atomicAdd(dst + 3, o.w);
                }
            }
            gridbar();
            continue;
        }

        // ---- phase B: GEMM + fused epilogue (+ DT scatter-add) ----
        {
            const int nt0 = (n0 + 63) >> 6, nt1 = (n1 + 63) >> 6;
            const int ttot = (nt0 + nt1) << 3;
            for (int t = blockIdx.x; t < ttot; t += gridDim.x) {
                const int p = (t >= (nt0 << 3)) ? 1 : 0;
                const int loc = p ? (t - (nt0 << 3)) : t;
                const int rowtile = loc >> 3, jt = loc & 7;
                const int s = p ? s1 : s0;
                const int n = p ? n1 : n0;
                const int r0 = rowtile << 6;
                int nr = n - r0; if (nr > 64) nr = 64;
                const int j0 = jt << 6;
                const __half* __restrict__ U16p = g_U16[p];

                __syncthreads();
                if (tid < 64) {
                    int rloc = tid < nr ? tid : (nr - 1);
                    int pos = s + r0 + rloc;
                    int pk = g_rows[p][pos];
                    rpk[tid] = pk;
                    int b = pk >> 16, node = pk & 0xffff;
                    if (p == 0) {
                        rptr[tid] = g_aprev + ((size_t)pos << 9);
                        rsc[tid] = 1.f;
                        float pv = pvalid[node * Bc + b];
                        int par = pidx[node * Bc + b];
                        rpar[tid] = (pv != 0.f) ? g_pos0[b][par] : -1;
                    } else {
                        int par = pidx[node * Bc + b];
                        rptr[tid] = out + ((size_t)(b * Lc + par) << 10) + Hc;
                        rsc[tid] = pvalid[node * Bc + b];
                        rpar[tid] = -1;
                    }
                }
                __syncthreads();

                float acc[2][6][4];
#pragma unroll
                for (int mi = 0; mi < 2; mi++)
#pragma unroll
                    for (int ni = 0; ni < 6; ni++)
#pragma unroll
                        for (int q = 0; q < 4; q++) acc[mi][ni][q] = 0.f;

                auto issueB = [&](int c, int st) {
                    const int kc = c << 5;
#pragma unroll
                    for (int l2 = 0; l2 < 3; ++l2) {
                        int slot = tid + (l2 << 8);
                        int row = slot >> 2, q = slot & 3;
                        int gate = row >> 6, j = row & 63;
                        cpa16(&B2s[st * 3840 + row * 20 + q * 4],
                              U16p + (size_t)(gate * Hc + j0 + j) * Hc + kc + q * 8);
                    }
                    cpa_commit();
                };

                issueB(0, 0);
                {
#pragma unroll
                    for (int l2 = 0; l2 < 2; ++l2) {
                        int slot = tid + (l2 << 8);
                        int row = slot >> 3, c4 = (slot & 7) << 2;
                        float4 v = *(const float4*)(rptr[row] + c4);
                        float sc = rsc[row];
                        uint2 u;
                        u.x = pack_h2(v.x * sc, v.y * sc);
                        u.y = pack_h2(v.z * sc, v.w * sc);
                        *(uint2*)&A2s[row * 20 + (c4 >> 1)] = u;
                    }
                }

                for (int c = 0; c < 16; ++c) {
                    const int st = c & 1;
                    if (c < 15) issueB(c + 1, st ^ 1);
                    float4 areg[2];
                    if (c < 15) {
                        const int kc = (c + 1) << 5;
#pragma unroll
                        for (int l2 = 0; l2 < 2; ++l2) {
                            int slot = tid + (l2 << 8);
                            int row = slot >> 3, c4 = (slot & 7) << 2;
                            areg[l2] = *(const float4*)(rptr[row] + kc + c4);
                        }
                    }
                    if (c < 15) cpa_wait<1>(); else cpa_wait<0>();
                    __syncthreads();
#pragma unroll
                    for (int ss = 0; ss < 2; ++ss) {
                        const int kpb = ss << 3;
                        unsigned af[2][4], bf[6][2];
#pragma unroll
                        for (int mi = 0; mi < 2; ++mi) {
                            int m = wm * 32 + mi * 16;
                            af[mi][0] = A2s[st * 1280 + (m + g) * 20 + kpb + tg];
                            af[mi][1] = A2s[st * 1280 + (m + g + 8) * 20 + kpb + tg];
                            af[mi][2] = A2s[st * 1280 + (m + g) * 20 + kpb + tg + 4];
                            af[mi][3] = A2s[st * 1280 + (m + g + 8) * 20 + kpb + tg + 4];
                        }
#pragma unroll
                        for (int ni = 0; ni < 6; ++ni) {
                            int nn = wn * 48 + ni * 8 + g;
                            bf[ni][0] = B2s[st * 3840 + nn * 20 + kpb + tg];
                            bf[ni][1] = B2s[st * 3840 + nn * 20 + kpb + tg + 4];
                        }
#pragma unroll
                        for (int mi = 0; mi < 2; ++mi)
#pragma unroll
                            for (int ni = 0; ni < 6; ++ni)
                                mma16(acc[mi][ni], af[mi], bf[ni]);
                    }
                    if (c < 15) {
#pragma unroll
                        for (int l2 = 0; l2 < 2; ++l2) {
                            int slot = tid + (l2 << 8);
                            int row = slot >> 3, c4 = (slot & 7) << 2;
                            float sc = rsc[row];
                            float4 v = areg[l2];
                            uint2 u;
                            u.x = pack_h2(v.x * sc, v.y * sc);
                            u.y = pack_h2(v.z * sc, v.w * sc);
                            *(uint2*)&A2s[(st ^ 1) * 1280 + row * 20 + (c4 >> 1)] = u;
                        }
                    }
                    __syncthreads();
                }

                // fused GRU epilogue via staged C (two 32-row halves)
#pragma unroll
                for (int half = 0; half < 2; ++half) {
                    if (wm == half) {
#pragma unroll
                        for (int mi = 0; mi < 2; ++mi)
#pragma unroll
                            for (int ni = 0; ni < 6; ++ni) {
                                int r = mi * 16 + g;
                                int c = wn * 48 + ni * 8 + 2 * tg;
                                Cst[r * 196 + c]           = acc[mi][ni][0];
                                Cst[r * 196 + c + 1]       = acc[mi][ni][1];
                                Cst[(r + 8) * 196 + c]     = acc[mi][ni][2];
                                Cst[(r + 8) * 196 + c + 1] = acc[mi][ni][3];
                            }
                    }
                    __syncthreads();
#pragma unroll
                    for (int l2 = 0; l2 < 8; ++l2) {
                        int flat = tid + (l2 << 8);
                        int rl = flat >> 6, j = flat & 63;
                        int rloc = half * 32 + rl;
                        if (rloc < nr) {
                            int pk = rpk[rloc];
                            int b = pk >> 16, node = pk & 0xffff;
                            const float* xrow = g_xg +
                                ((size_t)((p * Lc + node) * Bc + b)) * G3c + j0;
                            float hr = Cst[rl * 196 + j];
                            float hz = Cst[rl * 196 + 64 + j];
                            float hg = Cst[rl * 196 + 128 + j];
                            float hp = rptr[rloc][j0 + j] * rsc[rloc];
                            float r = sigf(xrow[j] + hr);
                            float z = sigf(xrow[Hc + j] + hz);
                            float nn2 = tanhfast(xrow[2 * Hc + j] + r * hg);
                            float hnew = (1.f - z) * nn2 + z * hp;
                            out[((size_t)(b * Lc + node) << 10) + (p << 9) + j0 + j] =
                                hnew;
                            int pp = rpar[rloc];
                            if (pp >= 0)
                                atomicAdd(&g_aprev[((size_t)pp << 9) + j0 + j], hnew);
                        }
                    }
                    __syncthreads();
                }
            }
        }
        gridbar();
    }
}

// ---------------------------------------------------------------------------
__global__ __launch_bounds__(256) void root_gather(
    const int* __restrict__ root_index, float* __restrict__ out)
{
    int i = blockIdx.x * 256 + threadIdx.x;
    int b = i >> 10;
    int j = i & 1023;
    int r = root_index[b];
    out[(size_t)Bc * Lc * OUT2H + (size_t)b * OUT2H + j] =
        out[((size_t)b * Lc + r) * OUT2H + j];
}

// ---------------------------------------------------------------------------
extern "C" void kernel_launch(void* const* d_in, const int* in_sizes, int n_in,
                              void* d_out, int out_size)
{
    const float* emb       = (const float*)d_in[0];
    /* indexes d_in[1], child_mask d_in[2] unused (parent pointers suffice) */
    const int*   td_pidx   = (const int*)  d_in[4];
    const float* td_pvalid = (const float*)d_in[5];
    const int*   root_idx  = (const int*)  d_in[6];
    const float* dt_Wx     = (const float*)d_in[7];
    const float* dt_Uh     = (const float*)d_in[8];
    const float* dt_b      = (const float*)d_in[9];
    const float* td_Wx     = (const float*)d_in[10];
    const float* td_Uh     = (const float*)d_in[11];
    const float* td_b      = (const float*)d_in[12];
    float* out = (float*)d_out;

    int sms = 148;
    cudaDeviceGetAttribute(&sms, cudaDevAttrMultiProcessorCount, 0);
    int NB = sms * 2;

    PcvtAll<<<19456, 256>>>(emb, dt_Uh, td_Uh, dt_Wx, td_Wx);   // 1
    Pprep<<<128, 256>>>(td_pidx);                               // 2
    Pscan3<<<2, 1024>>>();                                      // 3
    mega<<<NB, 256>>>(td_pidx, td_pvalid, dt_b, td_b, out);     // 4 (profiled)
    root_gather<<<(Bc * OUT2H) / 256, 256>>>(root_idx, out);    // 5
}

// round 16
// speedup vs baseline: 1.0498x; 1.0498x over previous
#include <cuda_runtime.h>
#include <cuda_fp16.h>
#include <math.h>

#define Lc   256
#define Bc   128
#define Dc   512
#define Hc   512
#define G3c  1536      // 3*H
#define OUT2H 1024     // 2*H
#define MAXL 256
#define NROWS (Lc*Bc)  // 32768

// ------------------------- static device scratch ---------------------------
__device__ float g_xg[(size_t)2 * Lc * Bc * G3c];          // ~403 MB
__device__ float g_aprev[(size_t)NROWS * Hc];              // DT child sums (fp32)
__device__ __align__(16) __half g_emb16[(size_t)NROWS * Dc];      // fp16 emb [row][k]
__device__ __align__(16) __half g_U16[2][(size_t)G3c * Hc];       // fp16 Uh^T [n][k]
__device__ __align__(16) __half g_W16[2][(size_t)G3c * Hc];       // fp16 Wx^T [n][k]
__device__ int   g_lvl[2][Bc][Lc];
__device__ int   g_cnt[2][MAXL][Bc];
__device__ int   g_off[2][MAXL * Bc];
__device__ int   g_lvloff[2][MAXL + 1];
__device__ int   g_rows[2][NROWS];                         // (b<<16)|node
__device__ int   g_pos0[Bc][Lc];                           // DT node -> level pos
__device__ int   g_nlvl[2];
__device__ int   g_nsteps;
__device__ int   g_choff[Bc][Lc + 1];
__device__ int   g_chlist[Bc][Lc];

__device__ volatile unsigned g_gen;
__device__ unsigned g_barcnt;

__device__ __forceinline__ void gridbar() {
    __syncthreads();
    if (threadIdx.x == 0) {
        unsigned gen = g_gen;
        __threadfence();
        unsigned old = atomicInc(&g_barcnt, gridDim.x - 1);
        if (old == gridDim.x - 1) {
            __threadfence();
            g_gen = gen + 1;
        } else {
            while (g_gen == gen) { __nanosleep(32); }
            __threadfence();
        }
    }
    __syncthreads();
}

// ------------------------- helpers -----------------------------------------
__device__ __forceinline__ unsigned pack_h2(float a, float b) {
    __half2 h = __floats2half2_rn(a, b);
    return *(unsigned*)&h;
}
__device__ __forceinline__ void mma16(float* c, const unsigned* a, const unsigned* b) {
    asm volatile(
        "mma.sync.aligned.m16n8k16.row.col.f32.f16.f16.f32 "
        "{%0,%1,%2,%3},{%4,%5,%6,%7},{%8,%9},{%0,%1,%2,%3};\n"
        : "+f"(c[0]), "+f"(c[1]), "+f"(c[2]), "+f"(c[3])
        : "r"(a[0]), "r"(a[1]), "r"(a[2]), "r"(a[3]), "r"(b[0]), "r"(b[1]));
}
__device__ __forceinline__ void cpa16(void* smem, const void* g) {
    unsigned s = (unsigned)__cvta_generic_to_shared(smem);
    asm volatile("cp.async.cg.shared.global [%0], [%1], 16;\n" :: "r"(s), "l"(g));
}
__device__ __forceinline__ void cpa_commit() {
    asm volatile("cp.async.commit_group;\n");
}
template <int N> __device__ __forceinline__ void cpa_wait() {
    asm volatile("cp.async.wait_group %0;\n" :: "n"(N));
}
__device__ __forceinline__ float sigf(float x) { return 1.f / (1.f + __expf(-x)); }
__device__ __forceinline__ float tanhfast(float x) { return 2.f * sigf(2.f * x) - 1.f; }

// ---------------- merged pre-pass: zero + emb cvt + weight transposes -------
__global__ __launch_bounds__(256) void PcvtAll(
    const float* __restrict__ emb,
    const float* __restrict__ U0, const float* __restrict__ U1,
    const float* __restrict__ W0, const float* __restrict__ W1)
{
    const int bx = blockIdx.x;
    if (bx < 8192) {
        size_t i = ((size_t)bx * 256 + threadIdx.x) * 8;
        float4 v0 = *(const float4*)&emb[i];
        float4 v1 = *(const float4*)&emb[i + 4];
        uint4 u;
        u.x = pack_h2(v0.x, v0.y); u.y = pack_h2(v0.z, v0.w);
        u.z = pack_h2(v1.x, v1.y); u.w = pack_h2(v1.z, v1.w);
        *(uint4*)&g_emb16[i] = u;
    } else if (bx < 11264) {
        __shared__ float sm[32][33];
        const int r = bx - 8192;
        const int w = r / 768;
        const int rr = r - w * 768;
        const float* src = (w == 0) ? U0 : (w == 1) ? U1 : (w == 2) ? W0 : W1;
        __half* dst = (w == 0) ? g_U16[0] : (w == 1) ? g_U16[1]
                    : (w == 2) ? g_W16[0] : g_W16[1];
        const int n0 = (rr % 48) * 32, k0 = (rr / 48) * 32;
        const int tx = threadIdx.x & 31, ty = threadIdx.x >> 5;
#pragma unroll
        for (int i = 0; i < 4; i++)
            sm[ty + 8 * i][tx] = src[(size_t)(k0 + ty + 8 * i) * G3c + n0 + tx];
        __syncthreads();
#pragma unroll
        for (int i = 0; i < 4; i++)
            dst[(size_t)(n0 + ty + 8 * i) * Hc + k0 + tx] =
                __float2half_rn(sm[tx][ty + 8 * i]);
    } else {
        size_t i = ((size_t)(bx - 11264) * 256 + threadIdx.x) * 8;
        float4 z = make_float4(0.f, 0.f, 0.f, 0.f);
        *(float4*)&g_aprev[i] = z;
        *(float4*)&g_aprev[i + 4] = z;
    }
}

// --------------------------- preprocessing ---------------------------------
__global__ __launch_bounds__(256) void Pprep(const int* __restrict__ pidx) {
    __shared__ int par[256], anc[256], dst[256], hgt[256];
    __shared__ int c0[256], c1[256], tmpc[256], cur[256], loff[257];
    __shared__ int mxd;
    const int b = blockIdx.x, i = threadIdx.x;
    par[i] = (i == 0) ? 0 : pidx[i * Bc + b];
    c0[i] = 0; c1[i] = 0; tmpc[i] = 0; hgt[i] = 0;
    if (i == 0) mxd = 0;
    __syncthreads();
    anc[i] = par[i];
    dst[i] = (i == 0) ? 0 : 1;
    __syncthreads();
#pragma unroll
    for (int r = 0; r < 8; ++r) {
        int a = anc[i];
        int nd = dst[i] + dst[a];
        int na = anc[a];
        __syncthreads();
        dst[i] = nd; anc[i] = na;
        __syncthreads();
    }
    const int depth = dst[i];
    atomicMax(&mxd, depth);
    if (i == 0) {
        for (int j = 255; j >= 1; --j) {
            int p = par[j], v = hgt[j] + 1;
            if (v > hgt[p]) hgt[p] = v;
        }
    }
    __syncthreads();
    const int h = hgt[i];
    atomicAdd(&c0[h], 1);
    atomicAdd(&c1[depth], 1);
    g_lvl[0][b][i] = h;
    g_lvl[1][b][i] = depth;
    if (i > 0) atomicAdd(&tmpc[par[i]], 1);
    __syncthreads();
    g_cnt[0][i][b] = c0[i];
    g_cnt[1][i][b] = c1[i];
    if (i == 0) {
        atomicMax(&g_nlvl[0], hgt[0] + 1);
        atomicMax(&g_nlvl[1], mxd + 1);
        int run = 0;
        loff[0] = 0;
        for (int p2 = 0; p2 < Lc; ++p2) {
            run += tmpc[p2]; loff[p2 + 1] = run; cur[p2] = 0;
        }
        for (int j = 1; j < Lc; ++j) {
            int p2 = par[j];
            g_chlist[b][loff[p2] + cur[p2]++] = j;
        }
    }
    __syncthreads();
    g_choff[b][i] = loff[i];
    if (i == 0) g_choff[b][Lc] = loff[Lc];
}

// exclusive scan; one block per pass, counts cached in registers (int4 loads)
__global__ __launch_bounds__(1024) void Pscan3() {
    __shared__ int wsum[32];
    const int p = blockIdx.x;
    const int tid = threadIdx.x;
    const int lane = tid & 31, wid = tid >> 5;
    const int* cnt = &g_cnt[p][0][0];
    int* off = &g_off[p][0];
    const int base = tid * 32;
    int vals[32];
#pragma unroll
    for (int k = 0; k < 8; ++k) {
        int4 v = *(const int4*)&cnt[base + k * 4];
        vals[k * 4 + 0] = v.x; vals[k * 4 + 1] = v.y;
        vals[k * 4 + 2] = v.z; vals[k * 4 + 3] = v.w;
    }
    int s = 0;
#pragma unroll
    for (int k = 0; k < 32; ++k) s += vals[k];
    int v = s;
#pragma unroll
    for (int d = 1; d < 32; d <<= 1) {
        int t2 = __shfl_up_sync(0xffffffffu, v, d);
        if (lane >= d) v += t2;
    }
    if (lane == 31) wsum[wid] = v;
    __syncthreads();
    if (wid == 0) {
        int w = wsum[lane];
#pragma unroll
        for (int d = 1; d < 32; d <<= 1) {
            int t2 = __shfl_up_sync(0xffffffffu, w, d);
            if (lane >= d) w += t2;
        }
        wsum[lane] = w;
    }
    __syncthreads();
    int run = v - s + (wid ? wsum[wid - 1] : 0);
    if ((tid & 3) == 0) g_lvloff[p][tid >> 2] = run;
#pragma unroll
    for (int k = 0; k < 32; ++k) { off[base + k] = run; run += vals[k]; }
    if (tid == 0) {
        g_lvloff[p][MAXL] = NROWS;
        if (p == 0) {
            int a = g_nlvl[0], c = g_nlvl[1];
            g_nsteps = a > c ? a : c;
        }
    }
}

__global__ __launch_bounds__(256) void Pscatter2() {
    __shared__ int cur[256], lv[256], lo[256];
    const int p = blockIdx.x >> 7, b = blockIdx.x & 127;
    const int i = threadIdx.x;
    cur[i] = 0;
    lv[i] = g_lvl[p][b][i];
    lo[i] = g_off[p][i * Bc + b];
    __syncthreads();
    if (i == 0) {
        for (int j = 0; j < Lc; ++j) {
            int l = lv[j];
            int pos = lo[l] + cur[l]++;
            g_rows[p][pos] = (b << 16) | j;
            if (p == 0) g_pos0[b][j] = pos;
        }
    }
}

// ---------------------------------------------------------------------------
// XG = emb @ Wx + b, fp16 mma m16n8k16 + cp.async double buffer (proven).
// ---------------------------------------------------------------------------
__global__ __launch_bounds__(256, 2) void xg_gemm3(
    const float* __restrict__ bias0, const float* __restrict__ bias1)
{
    __shared__ unsigned A2s[2][128 * 20];
    __shared__ unsigned B2s[2][128 * 20];

    const int pass = blockIdx.z;
    const __half* __restrict__ W = g_W16[pass];
    const float* __restrict__ bias = pass ? bias1 : bias0;
    float* C = g_xg + (size_t)pass * Lc * Bc * G3c;

    const int m0 = blockIdx.y * 128;
    const int n0b = blockIdx.x * 128;
    const int tid = threadIdx.x;
    const int lane = tid & 31, wid = tid >> 5;
    const int g = lane >> 2, tg = lane & 3;
    const int wm = wid >> 2, wn = wid & 3;

    float acc[4][4][4];
#pragma unroll
    for (int mi = 0; mi < 4; mi++)
#pragma unroll
        for (int ni = 0; ni < 4; ni++)
#pragma unroll
            for (int q = 0; q < 4; q++) acc[mi][ni][q] = 0.f;

    auto issue = [&](int c, int st) {
        const int kc = c << 5;
#pragma unroll
        for (int l2 = 0; l2 < 2; ++l2) {
            int slot = tid + (l2 << 8);
            int row = slot >> 2, q = slot & 3;
            cpa16(&A2s[st][row * 20 + q * 4],
                  g_emb16 + (size_t)(m0 + row) * Dc + kc + q * 8);
        }
#pragma unroll
        for (int l2 = 0; l2 < 2; ++l2) {
            int slot = tid + (l2 << 8);
            int row = slot >> 2, q = slot & 3;
            cpa16(&B2s[st][row * 20 + q * 4],
                  W + (size_t)(n0b + row) * Hc + kc + q * 8);
        }
        cpa_commit();
    };

    issue(0, 0);
    for (int c = 0; c < 16; ++c) {
        const int st = c & 1;
        if (c < 15) issue(c + 1, st ^ 1);
        if (c < 15) cpa_wait<1>(); else cpa_wait<0>();
        __syncthreads();
#pragma unroll
        for (int s = 0; s < 2; ++s) {
            const int kpb = s << 3;
            unsigned af[4][4], bf[4][2];
#pragma unroll
            for (int mi = 0; mi < 4; ++mi) {
                int m = wm * 64 + mi * 16;
                af[mi][0] = A2s[st][(m + g) * 20 + kpb + tg];
                af[mi][1] = A2s[st][(m + g + 8) * 20 + kpb + tg];
                af[mi][2] = A2s[st][(m + g) * 20 + kpb + tg + 4];
                af[mi][3] = A2s[st][(m + g + 8) * 20 + kpb + tg + 4];
            }
#pragma unroll
            for (int ni = 0; ni < 4; ++ni) {
                int nn = wn * 32 + ni * 8 + g;
                bf[ni][0] = B2s[st][nn * 20 + kpb + tg];
                bf[ni][1] = B2s[st][nn * 20 + kpb + tg + 4];
            }
#pragma unroll
            for (int mi = 0; mi < 4; ++mi)
#pragma unroll
                for (int ni = 0; ni < 4; ++ni)
                    mma16(acc[mi][ni], af[mi], bf[ni]);
        }
        __syncthreads();
    }

#pragma unroll
    for (int mi = 0; mi < 4; ++mi)
#pragma unroll
        for (int ni = 0; ni < 4; ++ni) {
            int row = m0 + wm * 64 + mi * 16 + g;
            int col = n0b + wn * 32 + ni * 8 + 2 * tg;
            float b0v = bias[col], b1v = bias[col + 1];
            C[(size_t)row * G3c + col]           = acc[mi][ni][0] + b0v;
            C[(size_t)row * G3c + col + 1]       = acc[mi][ni][1] + b1v;
            C[(size_t)(row + 8) * G3c + col]     = acc[mi][ni][2] + b0v;
            C[(size_t)(row + 8) * G3c + col + 1] = acc[mi][ni][3] + b1v;
        }
}

// ---------------------------------------------------------------------------
// Persistent wavefront kernel (R14 structure) with K-chunk = 64 via dynamic
// smem: 8 chunks instead of 16 -> half the syncs, 2x mma per exposed window.
// dyn smem (75008 B):
//   A2s @0      : 2 x 64 x 36 u32  = 18432
//   B2s @18432  : 2 x 192 x 36 u32 = 55296   (Cst 32x196 f32 unions stage 0)
//   rptr @73728 (512) | rsc @74240 (256) | rpk @74496 (256) | rpar @74752 (256)
// ---------------------------------------------------------------------------
__global__ __launch_bounds__(256, 2) void mega(
    const int* __restrict__ pidx, const float* __restrict__ pvalid,
    float* __restrict__ out)
{
    extern __shared__ __align__(16) char dyn[];
    unsigned* A2s = (unsigned*)dyn;                      // [2][64*36]
    unsigned* B2s = (unsigned*)(dyn + 18432);            // [2][192*36]
    float*    Cst = (float*)(dyn + 18432);               // [32*196]
    const float** rptr = (const float**)(dyn + 73728);   // [64]
    float* rsc = (float*)(dyn + 74240);                  // [64]
    int*   rpk = (int*)(dyn + 74496);                    // [64]
    int*   rpar = (int*)(dyn + 74752);                   // [64]

    const int tid = threadIdx.x;
    const int lane = tid & 31, wid = tid >> 5;
    const int g = lane >> 2, tg = lane & 3;
    const int wm = wid >> 2, wn = wid & 3;      // 2 x 4 warps
    const int nsteps = g_nsteps;

    for (int l = 0; l < nsteps; ++l) {
        const int s0 = g_lvloff[0][l], e0 = g_lvloff[0][l + 1];
        const int s1 = g_lvloff[1][l], e1 = g_lvloff[1][l + 1];
        const int n0 = e0 - s0, n1 = e1 - s1;

        if (l == 0) {
            // ---- level-0 shortcut + scatter-add to parents (DT) ----
            int total = (n0 + n1) << 7;   // 128 float4 per row
            for (int u = blockIdx.x * 256 + tid; u < total; u += gridDim.x * 256) {
                int rl = u >> 7, k4 = (u & 127) << 2;
                int p2, pos;
                if (rl < n0) { p2 = 0; pos = s0 + rl; }
                else         { p2 = 1; pos = s1 + (rl - n0); }
                int pk = g_rows[p2][pos];
                int b = pk >> 16, node = pk & 0xffff;
                const float* xrow = g_xg +
                    ((size_t)((p2 * Lc + node) * Bc + b)) * G3c;
                float4 xz = *(const float4*)&xrow[Hc + k4];
                float4 xn = *(const float4*)&xrow[2 * Hc + k4];
                float4 o;
                o.x = (1.f - sigf(xz.x)) * tanhfast(xn.x);
                o.y = (1.f - sigf(xz.y)) * tanhfast(xn.y);
                o.z = (1.f - sigf(xz.z)) * tanhfast(xn.z);
                o.w = (1.f - sigf(xz.w)) * tanhfast(xn.w);
                *(float4*)&out[((size_t)(b * Lc + node) << 10) + (p2 << 9) + k4] = o;
                if (p2 == 0) {
                    int par = pidx[node * Bc + b];
                    int ppos = g_pos0[b][par];
                    float* dst = g_aprev + ((size_t)ppos << 9) + k4;
                    atomicAdd(dst + 0, o.x);
                    atomicAdd(dst + 1, o.y);
                    atomicAdd(dst + 2, o.z);
                    atomicAdd(dst + 3, o.w);
                }
            }
            gridbar();
            continue;
        }

        // ---- phase B: GEMM + fused epilogue (+ DT scatter-add) ----
        {
            const int nt0 = (n0 + 63) >> 6, nt1 = (n1 + 63) >> 6;
            const int ttot = (nt0 + nt1) << 3;
            for (int t = blockIdx.x; t < ttot; t += gridDim.x) {
                const int p = (t >= (nt0 << 3)) ? 1 : 0;
                const int loc = p ? (t - (nt0 << 3)) : t;
                const int rowtile = loc >> 3, jt = loc & 7;
                const int s = p ? s1 : s0;
                const int n = p ? n1 : n0;
                const int r0 = rowtile << 6;
                int nr = n - r0; if (nr > 64) nr = 64;
                const int j0 = jt << 6;
                const __half* __restrict__ U16p = g_U16[p];

                __syncthreads();
                if (tid < 64) {
                    int rloc = tid < nr ? tid : (nr - 1);
                    int pos = s + r0 + rloc;
                    int pk = g_rows[p][pos];
                    rpk[tid] = pk;
                    int b = pk >> 16, node = pk & 0xffff;
                    if (p == 0) {
                        rptr[tid] = g_aprev + ((size_t)pos << 9);
                        rsc[tid] = 1.f;
                        float pv = pvalid[node * Bc + b];
                        int par = pidx[node * Bc + b];
                        rpar[tid] = (pv != 0.f) ? g_pos0[b][par] : -1;
                    } else {
                        int par = pidx[node * Bc + b];
                        rptr[tid] = out + ((size_t)(b * Lc + par) << 10) + Hc;
                        rsc[tid] = pvalid[node * Bc + b];
                        rpar[tid] = -1;
                    }
                }
                __syncthreads();

                float acc[2][6][4];
#pragma unroll
                for (int mi = 0; mi < 2; mi++)
#pragma unroll
                    for (int ni = 0; ni < 6; ni++)
#pragma unroll
                        for (int q = 0; q < 4; q++) acc[mi][ni][q] = 0.f;

                // B tile for 64-K chunk: 192 rows x 32 u32 = 1536 16B slots
                auto issueB = [&](int c, int st) {
                    const int kc = c << 6;
#pragma unroll
                    for (int l2 = 0; l2 < 6; ++l2) {
                        int slot = tid + (l2 << 8);
                        int row = slot >> 3, q = slot & 7;
                        int gate = row >> 6, j = row & 63;
                        cpa16(&B2s[st * 6912 + row * 36 + q * 4],
                              U16p + (size_t)(gate * Hc + j0 + j) * Hc + kc + q * 8);
                    }
                    cpa_commit();
                };

                issueB(0, 0);
                {
                    // fill A chunk 0: 64 rows x 64 floats = 1024 float4 slots
#pragma unroll
                    for (int l2 = 0; l2 < 4; ++l2) {
                        int slot = tid + (l2 << 8);
                        int row = slot >> 4, c4 = (slot & 15) << 2;
                        float4 v = *(const float4*)(rptr[row] + c4);
                        float sc = rsc[row];
                        uint2 u;
                        u.x = pack_h2(v.x * sc, v.y * sc);
                        u.y = pack_h2(v.z * sc, v.w * sc);
                        *(uint2*)&A2s[row * 36 + (c4 >> 1)] = u;
                    }
                }

                for (int c = 0; c < 8; ++c) {
                    const int st = c & 1;
                    if (c < 7) issueB(c + 1, st ^ 1);
                    float4 areg[4];
                    if (c < 7) {
                        const int kc = (c + 1) << 6;
#pragma unroll
                        for (int l2 = 0; l2 < 4; ++l2) {
                            int slot = tid + (l2 << 8);
                            int row = slot >> 4, c4 = (slot & 15) << 2;
                            areg[l2] = *(const float4*)(rptr[row] + kc + c4);
                        }
                    }
                    if (c < 7) cpa_wait<1>(); else cpa_wait<0>();
                    __syncthreads();
#pragma unroll
                    for (int ss = 0; ss < 4; ++ss) {
                        const int kpb = ss << 3;
                        unsigned af[2][4], bf[6][2];
#pragma unroll
                        for (int mi = 0; mi < 2; ++mi) {
                            int m = wm * 32 + mi * 16;
                            af[mi][0] = A2s[st * 2304 + (m + g) * 36 + kpb + tg];
                            af[mi][1] = A2s[st * 2304 + (m + g + 8) * 36 + kpb + tg];
                            af[mi][2] = A2s[st * 2304 + (m + g) * 36 + kpb + tg + 4];
                            af[mi][3] = A2s[st * 2304 + (m + g + 8) * 36 + kpb + tg + 4];
                        }
#pragma unroll
                        for (int ni = 0; ni < 6; ++ni) {
                            int nn = wn * 48 + ni * 8 + g;
                            bf[ni][0] = B2s[st * 6912 + nn * 36 + kpb + tg];
                            bf[ni][1] = B2s[st * 6912 + nn * 36 + kpb + tg + 4];
                        }
#pragma unroll
                        for (int mi = 0; mi < 2; ++mi)
#pragma unroll
                            for (int ni = 0; ni < 6; ++ni)
                                mma16(acc[mi][ni], af[mi], bf[ni]);
                    }
                    if (c < 7) {
#pragma unroll
                        for (int l2 = 0; l2 < 4; ++l2) {
                            int slot = tid + (l2 << 8);
                            int row = slot >> 4, c4 = (slot & 15) << 2;
                            float sc = rsc[row];
                            float4 v = areg[l2];
                            uint2 u;
                            u.x = pack_h2(v.x * sc, v.y * sc);
                            u.y = pack_h2(v.z * sc, v.w * sc);
                            *(uint2*)&A2s[(st ^ 1) * 2304 + row * 36 + (c4 >> 1)] = u;
                        }
                    }
                    __syncthreads();
                }

                // fused GRU epilogue via staged C (two 32-row halves)
#pragma unroll
                for (int half = 0; half < 2; ++half) {
                    if (wm == half) {
#pragma unroll
                        for (int mi = 0; mi < 2; ++mi)
#pragma unroll
                            for (int ni = 0; ni < 6; ++ni) {
                                int r = mi * 16 + g;
                                int c = wn * 48 + ni * 8 + 2 * tg;
                                Cst[r * 196 + c]           = acc[mi][ni][0];
                                Cst[r * 196 + c + 1]       = acc[mi][ni][1];
                                Cst[(r + 8) * 196 + c]     = acc[mi][ni][2];
                                Cst[(r + 8) * 196 + c + 1] = acc[mi][ni][3];
                            }
                    }
                    __syncthreads();
#pragma unroll
                    for (int l2 = 0; l2 < 8; ++l2) {
                        int flat = tid + (l2 << 8);
                        int rl = flat >> 6, j = flat & 63;
                        int rloc = half * 32 + rl;
                        if (rloc < nr) {
                            int pk = rpk[rloc];
                            int b = pk >> 16, node = pk & 0xffff;
                            const float* xrow = g_xg +
                                ((size_t)((p * Lc + node) * Bc + b)) * G3c + j0;
                            float hr = Cst[rl * 196 + j];
                            float hz = Cst[rl * 196 + 64 + j];
                            float hg = Cst[rl * 196 + 128 + j];
                            float hp = rptr[rloc][j0 + j] * rsc[rloc];
                            float r = sigf(xrow[j] + hr);
                            float z = sigf(xrow[Hc + j] + hz);
                            float nn2 = tanhfast(xrow[2 * Hc + j] + r * hg);
                            float hnew = (1.f - z) * nn2 + z * hp;
                            out[((size_t)(b * Lc + node) << 10) + (p << 9) + j0 + j] =
                                hnew;
                            int pp = rpar[rloc];
                            if (pp >= 0)
                                atomicAdd(&g_aprev[((size_t)pp << 9) + j0 + j], hnew);
                        }
                    }
                    __syncthreads();
                }
            }
        }
        gridbar();
    }
}

// ---------------------------------------------------------------------------
__global__ __launch_bounds__(256) void root_gather(
    const int* __restrict__ root_index, float* __restrict__ out)
{
    int i = blockIdx.x * 256 + threadIdx.x;
    int b = i >> 10;
    int j = i & 1023;
    int r = root_index[b];
    out[(size_t)Bc * Lc * OUT2H + (size_t)b * OUT2H + j] =
        out[((size_t)b * Lc + r) * OUT2H + j];
}

// ---------------------------------------------------------------------------
extern "C" void kernel_launch(void* const* d_in, const int* in_sizes, int n_in,
                              void* d_out, int out_size)
{
    const float* emb       = (const float*)d_in[0];
    /* indexes d_in[1], child_mask d_in[2] unused (parent pointers suffice) */
    const int*   td_pidx   = (const int*)  d_in[4];
    const float* td_pvalid = (const float*)d_in[5];
    const int*   root_idx  = (const int*)  d_in[6];
    const float* dt_Wx     = (const float*)d_in[7];
    const float* dt_Uh     = (const float*)d_in[8];
    const float* dt_b      = (const float*)d_in[9];
    const float* td_Wx     = (const float*)d_in[10];
    const float* td_Uh     = (const float*)d_in[11];
    const float* td_b      = (const float*)d_in[12];
    float* out = (float*)d_out;

    int sms = 148;
    cudaDeviceGetAttribute(&sms, cudaDevAttrMultiProcessorCount, 0);
    int NB = sms * 2;

    cudaFuncSetAttribute(mega,
        cudaFuncAttributeMaxDynamicSharedMemorySize, 75008);

    PcvtAll<<<19456, 256>>>(emb, dt_Uh, td_Uh, dt_Wx, td_Wx);
    Pprep<<<128, 256>>>(td_pidx);
    Pscan3<<<2, 1024>>>();
    Pscatter2<<<256, 256>>>();
    xg_gemm3<<<dim3(12, 256, 2), 256>>>(dt_b, td_b);
    mega<<<NB, 256, 75008>>>(td_pidx, td_pvalid, out);
    root_gather<<<(Bc * OUT2H) / 256, 256>>>(root_idx, out);
}

// round 17
// speedup vs baseline: 1.0849x; 1.0335x over previous
#include <cuda_runtime.h>
#include <cuda_fp16.h>
#include <math.h>

#define Lc   256
#define Bc   128
#define Dc   512
#define Hc   512
#define G3c  1536      // 3*H
#define OUT2H 1024     // 2*H
#define MAXL 256
#define NROWS (Lc*Bc)  // 32768

// ------------------------- static device scratch ---------------------------
__device__ float g_xg[(size_t)2 * Lc * Bc * G3c];          // ~403 MB
__device__ float g_aprev[(size_t)NROWS * Hc];              // DT child sums (fp32)
__device__ __align__(16) __half g_emb16[(size_t)NROWS * Dc];      // fp16 emb [row][k]
__device__ __align__(16) __half g_U16[2][(size_t)G3c * Hc];       // fp16 Uh^T [n][k]
__device__ __align__(16) __half g_W16[2][(size_t)G3c * Hc];       // fp16 Wx^T [n][k]
__device__ int   g_lvl[2][Bc][Lc];
__device__ int   g_cnt[2][MAXL][Bc];
__device__ int   g_off[2][MAXL * Bc];
__device__ int   g_lvloff[2][MAXL + 1];
__device__ int   g_rows[2][NROWS];                         // (b<<16)|node
__device__ int   g_pos0[Bc][Lc];                           // DT node -> level pos
__device__ int   g_nlvl[2];
__device__ int   g_nsteps;
__device__ int   g_choff[Bc][Lc + 1];
__device__ int   g_chlist[Bc][Lc];

__device__ volatile unsigned g_gen;
__device__ unsigned g_barcnt;

__device__ __forceinline__ void gridbar() {
    __syncthreads();
    if (threadIdx.x == 0) {
        unsigned gen = g_gen;
        __threadfence();
        unsigned old = atomicInc(&g_barcnt, gridDim.x - 1);
        if (old == gridDim.x - 1) {
            __threadfence();
            g_gen = gen + 1;
        } else {
            while (g_gen == gen) { __nanosleep(32); }
            __threadfence();
        }
    }
    __syncthreads();
}

// ------------------------- helpers -----------------------------------------
__device__ __forceinline__ unsigned pack_h2(float a, float b) {
    __half2 h = __floats2half2_rn(a, b);
    return *(unsigned*)&h;
}
__device__ __forceinline__ void mma16(float* c, const unsigned* a, const unsigned* b) {
    asm volatile(
        "mma.sync.aligned.m16n8k16.row.col.f32.f16.f16.f32 "
        "{%0,%1,%2,%3},{%4,%5,%6,%7},{%8,%9},{%0,%1,%2,%3};\n"
        : "+f"(c[0]), "+f"(c[1]), "+f"(c[2]), "+f"(c[3])
        : "r"(a[0]), "r"(a[1]), "r"(a[2]), "r"(a[3]), "r"(b[0]), "r"(b[1]));
}
__device__ __forceinline__ void cpa16(void* smem, const void* g) {
    unsigned s = (unsigned)__cvta_generic_to_shared(smem);
    asm volatile("cp.async.cg.shared.global [%0], [%1], 16;\n" :: "r"(s), "l"(g));
}
__device__ __forceinline__ void cpa_commit() {
    asm volatile("cp.async.commit_group;\n");
}
template <int N> __device__ __forceinline__ void cpa_wait() {
    asm volatile("cp.async.wait_group %0;\n" :: "n"(N));
}
__device__ __forceinline__ float sigf(float x) { return 1.f / (1.f + __expf(-x)); }
__device__ __forceinline__ float tanhfast(float x) { return 2.f * sigf(2.f * x) - 1.f; }

// ---------------- merged pre-pass: zero + emb cvt + weight transposes -------
__global__ __launch_bounds__(256) void PcvtAll(
    const float* __restrict__ emb,
    const float* __restrict__ U0, const float* __restrict__ U1,
    const float* __restrict__ W0, const float* __restrict__ W1)
{
    const int bx = blockIdx.x;
    if (bx < 8192) {
        size_t i = ((size_t)bx * 256 + threadIdx.x) * 8;
        float4 v0 = *(const float4*)&emb[i];
        float4 v1 = *(const float4*)&emb[i + 4];
        uint4 u;
        u.x = pack_h2(v0.x, v0.y); u.y = pack_h2(v0.z, v0.w);
        u.z = pack_h2(v1.x, v1.y); u.w = pack_h2(v1.z, v1.w);
        *(uint4*)&g_emb16[i] = u;
    } else if (bx < 11264) {
        __shared__ float sm[32][33];
        const int r = bx - 8192;
        const int w = r / 768;
        const int rr = r - w * 768;
        const float* src = (w == 0) ? U0 : (w == 1) ? U1 : (w == 2) ? W0 : W1;
        __half* dst = (w == 0) ? g_U16[0] : (w == 1) ? g_U16[1]
                    : (w == 2) ? g_W16[0] : g_W16[1];
        const int n0 = (rr % 48) * 32, k0 = (rr / 48) * 32;
        const int tx = threadIdx.x & 31, ty = threadIdx.x >> 5;
#pragma unroll
        for (int i = 0; i < 4; i++)
            sm[ty + 8 * i][tx] = src[(size_t)(k0 + ty + 8 * i) * G3c + n0 + tx];
        __syncthreads();
#pragma unroll
        for (int i = 0; i < 4; i++)
            dst[(size_t)(n0 + ty + 8 * i) * Hc + k0 + tx] =
                __float2half_rn(sm[tx][ty + 8 * i]);
    } else {
        size_t i = ((size_t)(bx - 11264) * 256 + threadIdx.x) * 8;
        float4 z = make_float4(0.f, 0.f, 0.f, 0.f);
        *(float4*)&g_aprev[i] = z;
        *(float4*)&g_aprev[i + 4] = z;
    }
}

// --------------------------- preprocessing ---------------------------------
__global__ __launch_bounds__(256) void Pprep(const int* __restrict__ pidx) {
    __shared__ int par[256], anc[256], dst[256], hgt[256];
    __shared__ int c0[256], c1[256], tmpc[256], cur[256], loff[257];
    __shared__ int mxd;
    const int b = blockIdx.x, i = threadIdx.x;
    par[i] = (i == 0) ? 0 : pidx[i * Bc + b];
    c0[i] = 0; c1[i] = 0; tmpc[i] = 0; hgt[i] = 0;
    if (i == 0) mxd = 0;
    __syncthreads();
    anc[i] = par[i];
    dst[i] = (i == 0) ? 0 : 1;
    __syncthreads();
#pragma unroll
    for (int r = 0; r < 8; ++r) {
        int a = anc[i];
        int nd = dst[i] + dst[a];
        int na = anc[a];
        __syncthreads();
        dst[i] = nd; anc[i] = na;
        __syncthreads();
    }
    const int depth = dst[i];
    atomicMax(&mxd, depth);
    if (i == 0) {
        for (int j = 255; j >= 1; --j) {
            int p = par[j], v = hgt[j] + 1;
            if (v > hgt[p]) hgt[p] = v;
        }
    }
    __syncthreads();
    const int h = hgt[i];
    atomicAdd(&c0[h], 1);
    atomicAdd(&c1[depth], 1);
    g_lvl[0][b][i] = h;
    g_lvl[1][b][i] = depth;
    if (i > 0) atomicAdd(&tmpc[par[i]], 1);
    __syncthreads();
    g_cnt[0][i][b] = c0[i];
    g_cnt[1][i][b] = c1[i];
    if (i == 0) {
        atomicMax(&g_nlvl[0], hgt[0] + 1);
        atomicMax(&g_nlvl[1], mxd + 1);
        int run = 0;
        loff[0] = 0;
        for (int p2 = 0; p2 < Lc; ++p2) {
            run += tmpc[p2]; loff[p2 + 1] = run; cur[p2] = 0;
        }
        for (int j = 1; j < Lc; ++j) {
            int p2 = par[j];
            g_chlist[b][loff[p2] + cur[p2]++] = j;
        }
    }
    __syncthreads();
    g_choff[b][i] = loff[i];
    if (i == 0) g_choff[b][Lc] = loff[Lc];
}

// exclusive scan; one block per pass, counts cached in registers (int4 loads)
__global__ __launch_bounds__(1024) void Pscan3() {
    __shared__ int wsum[32];
    const int p = blockIdx.x;
    const int tid = threadIdx.x;
    const int lane = tid & 31, wid = tid >> 5;
    const int* cnt = &g_cnt[p][0][0];
    int* off = &g_off[p][0];
    const int base = tid * 32;
    int vals[32];
#pragma unroll
    for (int k = 0; k < 8; ++k) {
        int4 v = *(const int4*)&cnt[base + k * 4];
        vals[k * 4 + 0] = v.x; vals[k * 4 + 1] = v.y;
        vals[k * 4 + 2] = v.z; vals[k * 4 + 3] = v.w;
    }
    int s = 0;
#pragma unroll
    for (int k = 0; k < 32; ++k) s += vals[k];
    int v = s;
#pragma unroll
    for (int d = 1; d < 32; d <<= 1) {
        int t2 = __shfl_up_sync(0xffffffffu, v, d);
        if (lane >= d) v += t2;
    }
    if (lane == 31) wsum[wid] = v;
    __syncthreads();
    if (wid == 0) {
        int w = wsum[lane];
#pragma unroll
        for (int d = 1; d < 32; d <<= 1) {
            int t2 = __shfl_up_sync(0xffffffffu, w, d);
            if (lane >= d) w += t2;
        }
        wsum[lane] = w;
    }
    __syncthreads();
    int run = v - s + (wid ? wsum[wid - 1] : 0);
    if ((tid & 3) == 0) g_lvloff[p][tid >> 2] = run;
#pragma unroll
    for (int k = 0; k < 32; ++k) { off[base + k] = run; run += vals[k]; }
    if (tid == 0) {
        g_lvloff[p][MAXL] = NROWS;
        if (p == 0) {
            int a = g_nlvl[0], c = g_nlvl[1];
            g_nsteps = a > c ? a : c;
        }
    }
}

__global__ __launch_bounds__(256) void Pscatter2() {
    __shared__ int cur[256], lv[256], lo[256];
    const int p = blockIdx.x >> 7, b = blockIdx.x & 127;
    const int i = threadIdx.x;
    cur[i] = 0;
    lv[i] = g_lvl[p][b][i];
    lo[i] = g_off[p][i * Bc + b];
    __syncthreads();
    if (i == 0) {
        for (int j = 0; j < Lc; ++j) {
            int l = lv[j];
            int pos = lo[l] + cur[l]++;
            g_rows[p][pos] = (b << 16) | j;
            if (p == 0) g_pos0[b][j] = pos;
        }
    }
}

// ---------------------------------------------------------------------------
// XG = emb @ Wx + b, fp16 mma m16n8k16; K-chunk = 64 via dynamic smem
// (8 chunks, half the syncs of the old 16x32 loop).
// dyn smem: XA 2 x 128 x 36 u32 = 36864 | XB same @36864  => 73728 B
// ---------------------------------------------------------------------------
__global__ __launch_bounds__(256, 2) void xg_gemm4(
    const float* __restrict__ bias0, const float* __restrict__ bias1)
{
    extern __shared__ __align__(16) char dynx[];
    unsigned* XA = (unsigned*)dynx;                      // [2][128*36]
    unsigned* XB = (unsigned*)(dynx + 36864);            // [2][128*36]

    const int pass = blockIdx.z;
    const __half* __restrict__ W = g_W16[pass];
    const float* __restrict__ bias = pass ? bias1 : bias0;
    float* C = g_xg + (size_t)pass * Lc * Bc * G3c;

    const int m0 = blockIdx.y * 128;
    const int n0b = blockIdx.x * 128;
    const int tid = threadIdx.x;
    const int lane = tid & 31, wid = tid >> 5;
    const int g = lane >> 2, tg = lane & 3;
    const int wm = wid >> 2, wn = wid & 3;

    float acc[4][4][4];
#pragma unroll
    for (int mi = 0; mi < 4; mi++)
#pragma unroll
        for (int ni = 0; ni < 4; ni++)
#pragma unroll
            for (int q = 0; q < 4; q++) acc[mi][ni][q] = 0.f;

    // one 64-K chunk: A/B each 128 rows x 64 halves = 1024 16B slots
    auto issue = [&](int c, int st) {
        const int kc = c << 6;
#pragma unroll
        for (int l2 = 0; l2 < 4; ++l2) {
            int slot = tid + (l2 << 8);
            int row = slot >> 3, q = slot & 7;
            cpa16(&XA[st * 4608 + row * 36 + q * 4],
                  g_emb16 + (size_t)(m0 + row) * Dc + kc + q * 8);
        }
#pragma unroll
        for (int l2 = 0; l2 < 4; ++l2) {
            int slot = tid + (l2 << 8);
            int row = slot >> 3, q = slot & 7;
            cpa16(&XB[st * 4608 + row * 36 + q * 4],
                  W + (size_t)(n0b + row) * Hc + kc + q * 8);
        }
        cpa_commit();
    };

    issue(0, 0);
    for (int c = 0; c < 8; ++c) {
        const int st = c & 1;
        if (c < 7) issue(c + 1, st ^ 1);
        if (c < 7) cpa_wait<1>(); else cpa_wait<0>();
        __syncthreads();
#pragma unroll
        for (int ss = 0; ss < 4; ++ss) {
            const int kpb = ss << 3;
            unsigned af[4][4], bf[4][2];
#pragma unroll
            for (int mi = 0; mi < 4; ++mi) {
                int m = wm * 64 + mi * 16;
                af[mi][0] = XA[st * 4608 + (m + g) * 36 + kpb + tg];
                af[mi][1] = XA[st * 4608 + (m + g + 8) * 36 + kpb + tg];
                af[mi][2] = XA[st * 4608 + (m + g) * 36 + kpb + tg + 4];
                af[mi][3] = XA[st * 4608 + (m + g + 8) * 36 + kpb + tg + 4];
            }
#pragma unroll
            for (int ni = 0; ni < 4; ++ni) {
                int nn = wn * 32 + ni * 8 + g;
                bf[ni][0] = XB[st * 4608 + nn * 36 + kpb + tg];
                bf[ni][1] = XB[st * 4608 + nn * 36 + kpb + tg + 4];
            }
#pragma unroll
            for (int mi = 0; mi < 4; ++mi)
#pragma unroll
                for (int ni = 0; ni < 4; ++ni)
                    mma16(acc[mi][ni], af[mi], bf[ni]);
        }
        __syncthreads();
    }

#pragma unroll
    for (int mi = 0; mi < 4; ++mi)
#pragma unroll
        for (int ni = 0; ni < 4; ++ni) {
            int row = m0 + wm * 64 + mi * 16 + g;
            int col = n0b + wn * 32 + ni * 8 + 2 * tg;
            float b0v = bias[col], b1v = bias[col + 1];
            C[(size_t)row * G3c + col]           = acc[mi][ni][0] + b0v;
            C[(size_t)row * G3c + col + 1]       = acc[mi][ni][1] + b1v;
            C[(size_t)(row + 8) * G3c + col]     = acc[mi][ni][2] + b0v;
            C[(size_t)(row + 8) * G3c + col + 1] = acc[mi][ni][3] + b1v;
        }
}

// ---------------------------------------------------------------------------
// Persistent wavefront kernel (R16-proven, K-chunk 64, level-0 shortcut,
// scatter-add child sums). dyn smem 75008 B.
// ---------------------------------------------------------------------------
__global__ __launch_bounds__(256, 2) void mega(
    const int* __restrict__ pidx, const float* __restrict__ pvalid,
    float* __restrict__ out)
{
    extern __shared__ __align__(16) char dyn[];
    unsigned* A2s = (unsigned*)dyn;                      // [2][64*36]
    unsigned* B2s = (unsigned*)(dyn + 18432);            // [2][192*36]
    float*    Cst = (float*)(dyn + 18432);               // [32*196]
    const float** rptr = (const float**)(dyn + 73728);   // [64]
    float* rsc = (float*)(dyn + 74240);                  // [64]
    int*   rpk = (int*)(dyn + 74496);                    // [64]
    int*   rpar = (int*)(dyn + 74752);                   // [64]

    const int tid = threadIdx.x;
    const int lane = tid & 31, wid = tid >> 5;
    const int g = lane >> 2, tg = lane & 3;
    const int wm = wid >> 2, wn = wid & 3;      // 2 x 4 warps
    const int nsteps = g_nsteps;

    for (int l = 0; l < nsteps; ++l) {
        const int s0 = g_lvloff[0][l], e0 = g_lvloff[0][l + 1];
        const int s1 = g_lvloff[1][l], e1 = g_lvloff[1][l + 1];
        const int n0 = e0 - s0, n1 = e1 - s1;

        if (l == 0) {
            // ---- level-0 shortcut + scatter-add to parents (DT) ----
            int total = (n0 + n1) << 7;   // 128 float4 per row
            for (int u = blockIdx.x * 256 + tid; u < total; u += gridDim.x * 256) {
                int rl = u >> 7, k4 = (u & 127) << 2;
                int p2, pos;
                if (rl < n0) { p2 = 0; pos = s0 + rl; }
                else         { p2 = 1; pos = s1 + (rl - n0); }
                int pk = g_rows[p2][pos];
                int b = pk >> 16, node = pk & 0xffff;
                const float* xrow = g_xg +
                    ((size_t)((p2 * Lc + node) * Bc + b)) * G3c;
                float4 xz = *(const float4*)&xrow[Hc + k4];
                float4 xn = *(const float4*)&xrow[2 * Hc + k4];
                float4 o;
                o.x = (1.f - sigf(xz.x)) * tanhfast(xn.x);
                o.y = (1.f - sigf(xz.y)) * tanhfast(xn.y);
                o.z = (1.f - sigf(xz.z)) * tanhfast(xn.z);
                o.w = (1.f - sigf(xz.w)) * tanhfast(xn.w);
                *(float4*)&out[((size_t)(b * Lc + node) << 10) + (p2 << 9) + k4] = o;
                if (p2 == 0) {
                    int par = pidx[node * Bc + b];
                    int ppos = g_pos0[b][par];
                    float* dst = g_aprev + ((size_t)ppos << 9) + k4;
                    atomicAdd(dst + 0, o.x);
                    atomicAdd(dst + 1, o.y);
                    atomicAdd(dst + 2, o.z);
                    atomicAdd(dst + 3, o.w);
                }
            }
            gridbar();
            continue;
        }

        // ---- phase B: GEMM + fused epilogue (+ DT scatter-add) ----
        {
            const int nt0 = (n0 + 63) >> 6, nt1 = (n1 + 63) >> 6;
            const int ttot = (nt0 + nt1) << 3;
            for (int t = blockIdx.x; t < ttot; t += gridDim.x) {
                const int p = (t >= (nt0 << 3)) ? 1 : 0;
                const int loc = p ? (t - (nt0 << 3)) : t;
                const int rowtile = loc >> 3, jt = loc & 7;
                const int s = p ? s1 : s0;
                const int n = p ? n1 : n0;
                const int r0 = rowtile << 6;
                int nr = n - r0; if (nr > 64) nr = 64;
                const int j0 = jt << 6;
                const __half* __restrict__ U16p = g_U16[p];

                __syncthreads();
                if (tid < 64) {
                    int rloc = tid < nr ? tid : (nr - 1);
                    int pos = s + r0 + rloc;
                    int pk = g_rows[p][pos];
                    rpk[tid] = pk;
                    int b = pk >> 16, node = pk & 0xffff;
                    if (p == 0) {
                        rptr[tid] = g_aprev + ((size_t)pos << 9);
                        rsc[tid] = 1.f;
                        float pv = pvalid[node * Bc + b];
                        int par = pidx[node * Bc + b];
                        rpar[tid] = (pv != 0.f) ? g_pos0[b][par] : -1;
                    } else {
                        int par = pidx[node * Bc + b];
                        rptr[tid] = out + ((size_t)(b * Lc + par) << 10) + Hc;
                        rsc[tid] = pvalid[node * Bc + b];
                        rpar[tid] = -1;
                    }
                }
                __syncthreads();

                float acc[2][6][4];
#pragma unroll
                for (int mi = 0; mi < 2; mi++)
#pragma unroll
                    for (int ni = 0; ni < 6; ni++)
#pragma unroll
                        for (int q = 0; q < 4; q++) acc[mi][ni][q] = 0.f;

                auto issueB = [&](int c, int st) {
                    const int kc = c << 6;
#pragma unroll
                    for (int l2 = 0; l2 < 6; ++l2) {
                        int slot = tid + (l2 << 8);
                        int row = slot >> 3, q = slot & 7;
                        int gate = row >> 6, j = row & 63;
                        cpa16(&B2s[st * 6912 + row * 36 + q * 4],
                              U16p + (size_t)(gate * Hc + j0 + j) * Hc + kc + q * 8);
                    }
                    cpa_commit();
                };

                issueB(0, 0);
                {
#pragma unroll
                    for (int l2 = 0; l2 < 4; ++l2) {
                        int slot = tid + (l2 << 8);
                        int row = slot >> 4, c4 = (slot & 15) << 2;
                        float4 v = *(const float4*)(rptr[row] + c4);
                        float sc = rsc[row];
                        uint2 u;
                        u.x = pack_h2(v.x * sc, v.y * sc);
                        u.y = pack_h2(v.z * sc, v.w * sc);
                        *(uint2*)&A2s[row * 36 + (c4 >> 1)] = u;
                    }
                }

                for (int c = 0; c < 8; ++c) {
                    const int st = c & 1;
                    if (c < 7) issueB(c + 1, st ^ 1);
                    float4 areg[4];
                    if (c < 7) {
                        const int kc = (c + 1) << 6;
#pragma unroll
                        for (int l2 = 0; l2 < 4; ++l2) {
                            int slot = tid + (l2 << 8);
                            int row = slot >> 4, c4 = (slot & 15) << 2;
                            areg[l2] = *(const float4*)(rptr[row] + kc + c4);
                        }
                    }
                    if (c < 7) cpa_wait<1>(); else cpa_wait<0>();
                    __syncthreads();
#pragma unroll
                    for (int ss = 0; ss < 4; ++ss) {
                        const int kpb = ss << 3;
                        unsigned af[2][4], bf[6][2];
#pragma unroll
                        for (int mi = 0; mi < 2; ++mi) {
                            int m = wm * 32 + mi * 16;
                            af[mi][0] = A2s[st * 2304 + (m + g) * 36 + kpb + tg];
                            af[mi][1] = A2s[st * 2304 + (m + g + 8) * 36 + kpb + tg];
                            af[mi][2] = A2s[st * 2304 + (m + g) * 36 + kpb + tg + 4];
                            af[mi][3] = A2s[st * 2304 + (m + g + 8) * 36 + kpb + tg + 4];
                        }
#pragma unroll
                        for (int ni = 0; ni < 6; ++ni) {
                            int nn = wn * 48 + ni * 8 + g;
                            bf[ni][0] = B2s[st * 6912 + nn * 36 + kpb + tg];
                            bf[ni][1] = B2s[st * 6912 + nn * 36 + kpb + tg + 4];
                        }
#pragma unroll
                        for (int mi = 0; mi < 2; ++mi)
#pragma unroll
                            for (int ni = 0; ni < 6; ++ni)
                                mma16(acc[mi][ni], af[mi], bf[ni]);
                    }
                    if (c < 7) {
#pragma unroll
                        for (int l2 = 0; l2 < 4; ++l2) {
                            int slot = tid + (l2 << 8);
                            int row = slot >> 4, c4 = (slot & 15) << 2;
                            float sc = rsc[row];
                            float4 v = areg[l2];
                            uint2 u;
                            u.x = pack_h2(v.x * sc, v.y * sc);
                            u.y = pack_h2(v.z * sc, v.w * sc);
                            *(uint2*)&A2s[(st ^ 1) * 2304 + row * 36 + (c4 >> 1)] = u;
                        }
                    }
                    __syncthreads();
                }

                // fused GRU epilogue via staged C (two 32-row halves)
#pragma unroll
                for (int half = 0; half < 2; ++half) {
                    if (wm == half) {
#pragma unroll
                        for (int mi = 0; mi < 2; ++mi)
#pragma unroll
                            for (int ni = 0; ni < 6; ++ni) {
                                int r = mi * 16 + g;
                                int c = wn * 48 + ni * 8 + 2 * tg;
                                Cst[r * 196 + c]           = acc[mi][ni][0];
                                Cst[r * 196 + c + 1]       = acc[mi][ni][1];
                                Cst[(r + 8) * 196 + c]     = acc[mi][ni][2];
                                Cst[(r + 8) * 196 + c + 1] = acc[mi][ni][3];
                            }
                    }
                    __syncthreads();
#pragma unroll
                    for (int l2 = 0; l2 < 8; ++l2) {
                        int flat = tid + (l2 << 8);
                        int rl = flat >> 6, j = flat & 63;
                        int rloc = half * 32 + rl;
                        if (rloc < nr) {
                            int pk = rpk[rloc];
                            int b = pk >> 16, node = pk & 0xffff;
                            const float* xrow = g_xg +
                                ((size_t)((p * Lc + node) * Bc + b)) * G3c + j0;
                            float hr = Cst[rl * 196 + j];
                            float hz = Cst[rl * 196 + 64 + j];
                            float hg = Cst[rl * 196 + 128 + j];
                            float hp = rptr[rloc][j0 + j] * rsc[rloc];
                            float r = sigf(xrow[j] + hr);
                            float z = sigf(xrow[Hc + j] + hz);
                            float nn2 = tanhfast(xrow[2 * Hc + j] + r * hg);
                            float hnew = (1.f - z) * nn2 + z * hp;
                            out[((size_t)(b * Lc + node) << 10) + (p << 9) + j0 + j] =
                                hnew;
                            int pp = rpar[rloc];
                            if (pp >= 0)
                                atomicAdd(&g_aprev[((size_t)pp << 9) + j0 + j], hnew);
                        }
                    }
                    __syncthreads();
                }
            }
        }
        gridbar();
    }
}

// ---------------------------------------------------------------------------
__global__ __launch_bounds__(256) void root_gather(
    const int* __restrict__ root_index, float* __restrict__ out)
{
    int i = blockIdx.x * 256 + threadIdx.x;
    int b = i >> 10;
    int j = i & 1023;
    int r = root_index[b];
    out[(size_t)Bc * Lc * OUT2H + (size_t)b * OUT2H + j] =
        out[((size_t)b * Lc + r) * OUT2H + j];
}

// ---------------------------------------------------------------------------
extern "C" void kernel_launch(void* const* d_in, const int* in_sizes, int n_in,
                              void* d_out, int out_size)
{
    const float* emb       = (const float*)d_in[0];
    /* indexes d_in[1], child_mask d_in[2] unused (parent pointers suffice) */
    const int*   td_pidx   = (const int*)  d_in[4];
    const float* td_pvalid = (const float*)d_in[5];
    const int*   root_idx  = (const int*)  d_in[6];
    const float* dt_Wx     = (const float*)d_in[7];
    const float* dt_Uh     = (const float*)d_in[8];
    const float* dt_b      = (const float*)d_in[9];
    const float* td_Wx     = (const float*)d_in[10];
    const float* td_Uh     = (const float*)d_in[11];
    const float* td_b      = (const float*)d_in[12];
    float* out = (float*)d_out;

    int sms = 148;
    cudaDeviceGetAttribute(&sms, cudaDevAttrMultiProcessorCount, 0);
    int NB = sms * 2;

    cudaFuncSetAttribute(xg_gemm4,
        cudaFuncAttributeMaxDynamicSharedMemorySize, 73728);
    cudaFuncSetAttribute(mega,
        cudaFuncAttributeMaxDynamicSharedMemorySize, 75008);

    PcvtAll<<<19456, 256>>>(emb, dt_Uh, td_Uh, dt_Wx, td_Wx);
    Pprep<<<128, 256>>>(td_pidx);
    Pscan3<<<2, 1024>>>();
    Pscatter2<<<256, 256>>>();
    xg_gemm4<<<dim3(12, 256, 2), 256, 73728>>>(dt_b, td_b);
    mega<<<NB, 256, 75008>>>(td_pidx, td_pvalid, out);
    root_gather<<<(Bc * OUT2H) / 256, 256>>>(root_idx, out);
}